// round 1
// baseline (speedup 1.0000x reference)
#include <cuda_runtime.h>

// Problem constants (fixed by reference setup)
#define TOKENS 8192
#define IN_F   4096
#define OUT_F  4096
#define RANK   16
#define LSCALE 2.0f        // lora_alpha / r = 32/16

// GEMM tiling
#define BM 128
#define BN 128
#define BK 16
#define XP 132             // Xs row pitch (pad vs 128 to break STS bank conflicts)
#define NT (IN_F / BK)     // 256 K-tiles

// Scratch for t = SCALING * (x @ A^T), shape [TOKENS][RANK]
__device__ float g_t[TOKENS * RANK];

// ---------------------------------------------------------------------------
// Kernel 1: t[m][r] = LSCALE * sum_k x[m][k] * A[r][k]
// Block = 256 threads = 16 r-lanes x 16 row-groups, each group owns 4 rows.
// x loads broadcast across the 16 r-lanes; A is tiny (256 KB) -> L1/L2 hits.
// ---------------------------------------------------------------------------
__global__ void __launch_bounds__(256) lora_t_kernel(
    const float* __restrict__ x, const float* __restrict__ loraA)
{
    const int tid = threadIdx.x;
    const int r   = tid & 15;
    const int grp = tid >> 4;
    const int m0  = blockIdx.x * 64 + grp * 4;

    const float4* A4 = reinterpret_cast<const float4*>(loraA + (size_t)r * IN_F);
    const float4* x0 = reinterpret_cast<const float4*>(x + (size_t)(m0 + 0) * IN_F);
    const float4* x1 = reinterpret_cast<const float4*>(x + (size_t)(m0 + 1) * IN_F);
    const float4* x2 = reinterpret_cast<const float4*>(x + (size_t)(m0 + 2) * IN_F);
    const float4* x3 = reinterpret_cast<const float4*>(x + (size_t)(m0 + 3) * IN_F);

    float a0 = 0.f, a1 = 0.f, a2 = 0.f, a3 = 0.f;
#pragma unroll 4
    for (int k = 0; k < IN_F / 4; k++) {
        float4 a = __ldg(&A4[k]);
        float4 v;
        v = __ldg(&x0[k]); a0 += v.x*a.x + v.y*a.y + v.z*a.z + v.w*a.w;
        v = __ldg(&x1[k]); a1 += v.x*a.x + v.y*a.y + v.z*a.z + v.w*a.w;
        v = __ldg(&x2[k]); a2 += v.x*a.x + v.y*a.y + v.z*a.z + v.w*a.w;
        v = __ldg(&x3[k]); a3 += v.x*a.x + v.y*a.y + v.z*a.z + v.w*a.w;
    }
    g_t[(size_t)(m0 + 0) * RANK + r] = LSCALE * a0;
    g_t[(size_t)(m0 + 1) * RANK + r] = LSCALE * a1;
    g_t[(size_t)(m0 + 2) * RANK + r] = LSCALE * a2;
    g_t[(size_t)(m0 + 3) * RANK + r] = LSCALE * a3;
}

// ---------------------------------------------------------------------------
// Kernel 2: out = x @ dequant(W)  +  t @ B^T  (epilogue)
// 128x128x16 tiles, 256 threads, 8x8 micro-tile, double-buffered SMEM.
// int4 dequant (GPTQ: W = s*(q - (z+1))) fused into the SMEM store stage.
// ---------------------------------------------------------------------------
__global__ void __launch_bounds__(256, 2) fused_gemm_kernel(
    const float* __restrict__ x,
    const int*   __restrict__ qweight,   // [IN_F/8][OUT_F], 8 int4 packed along K
    const int*   __restrict__ qzeros,    // [IN_F/128][OUT_F/8], 8 int4 packed along N
    const float* __restrict__ scales,    // [IN_F/128][OUT_F]
    const float* __restrict__ loraB,     // [OUT_F][RANK]
    float*       __restrict__ out)
{
    __shared__ float Xs[2][BK][XP];      // x tile, [k][m] transposed
    __shared__ float Ws[2][BK][BN];      // dequantized W tile, [k][n]

    const int tid = threadIdx.x;
    const int tx  = tid & 15;
    const int ty  = tid >> 4;
    const int n0  = blockIdx.x * BN;
    const int m0  = blockIdx.y * BM;

    // X tile load mapping: 512 float4s, thread covers tid and tid+256
    const int m_l0 = tid >> 2;           // rows 0..63
    const int c0   = tid & 3;            // float4 column within the 16-wide k-slab
    const int m_l1 = (tid + 256) >> 2;   // rows 64..127

    // W dequant mapping: thread owns one packed int32 (8 k-values at column nq)
    const int nq = tid & 127;
    const int kq = tid >> 7;             // 0/1 -> packed rows kt*2 + kq

    const float* xr0p = x + (size_t)(m0 + m_l0) * IN_F + c0 * 4;
    const float* xr1p = x + (size_t)(m0 + m_l1) * IN_F + c0 * 4;
    const int*   qwp  = qweight + n0 + nq;
    const int*   qzp  = qzeros + ((n0 + nq) >> 3);
    const float* scp  = scales + n0 + nq;
    const int zshift  = 4 * ((n0 + nq) & 7);

    float acc[8][8];
#pragma unroll
    for (int i = 0; i < 8; i++)
#pragma unroll
        for (int j = 0; j < 8; j++) acc[i][j] = 0.f;

    auto store_tile = [&](int b, float4 xA, float4 xB, int qwv, float sv, int zv) {
        Xs[b][c0 * 4 + 0][m_l0] = xA.x;
        Xs[b][c0 * 4 + 1][m_l0] = xA.y;
        Xs[b][c0 * 4 + 2][m_l0] = xA.z;
        Xs[b][c0 * 4 + 3][m_l0] = xA.w;
        Xs[b][c0 * 4 + 0][m_l1] = xB.x;
        Xs[b][c0 * 4 + 1][m_l1] = xB.y;
        Xs[b][c0 * 4 + 2][m_l1] = xB.z;
        Xs[b][c0 * 4 + 3][m_l1] = xB.w;
        const float nsz = -sv * (float)zv;   // -s*(z+1)
#pragma unroll
        for (int i = 0; i < 8; i++) {
            int q = (qwv >> (4 * i)) & 0xF;
            Ws[b][kq * 8 + i][nq] = fmaf((float)q, sv, nsz);
        }
    };

    auto compute_tile = [&](int b) {
#pragma unroll
        for (int kk = 0; kk < BK; kk++) {
            float a[8], bb[8];
            *reinterpret_cast<float4*>(&a[0])  = *reinterpret_cast<const float4*>(&Xs[b][kk][ty * 8]);
            *reinterpret_cast<float4*>(&a[4])  = *reinterpret_cast<const float4*>(&Xs[b][kk][ty * 8 + 4]);
            *reinterpret_cast<float4*>(&bb[0]) = *reinterpret_cast<const float4*>(&Ws[b][kk][tx * 8]);
            *reinterpret_cast<float4*>(&bb[4]) = *reinterpret_cast<const float4*>(&Ws[b][kk][tx * 8 + 4]);
#pragma unroll
            for (int i = 0; i < 8; i++)
#pragma unroll
                for (int j = 0; j < 8; j++)
                    acc[i][j] = fmaf(a[i], bb[j], acc[i][j]);
        }
    };

    // --- prologue: tile 0 ---
    {
        float4 xA = *reinterpret_cast<const float4*>(xr0p);
        float4 xB = *reinterpret_cast<const float4*>(xr1p);
        int   qwv = qwp[(size_t)kq * OUT_F];
        int    zw = qzp[0];
        int    zv = ((zw >> zshift) & 0xF) + 1;
        float  sv = scp[0];
        store_tile(0, xA, xB, qwv, sv, zv);
    }
    __syncthreads();

    int buf = 0;
    for (int kt = 0; kt < NT; kt++) {
        float4 nxA, nxB;
        int nqw = 0, nzv = 0;
        float nsv = 0.f;
        const bool more = (kt + 1 < NT);
        if (more) {
            const int kt1 = kt + 1;
            nxA = *reinterpret_cast<const float4*>(xr0p + kt1 * BK);
            nxB = *reinterpret_cast<const float4*>(xr1p + kt1 * BK);
            nqw = qwp[(size_t)(kt1 * 2 + kq) * OUT_F];
            const int g = kt1 >> 3;                 // group = (k / 128)
            int zw = qzp[(size_t)g * (OUT_F / 8)];
            nzv = ((zw >> zshift) & 0xF) + 1;
            nsv = scp[(size_t)g * OUT_F];
        }
        compute_tile(buf);
        if (more) store_tile(buf ^ 1, nxA, nxB, nqw, nsv, nzv);
        __syncthreads();
        buf ^= 1;
    }

    // --- LoRA epilogue: acc += t_tile @ B_tile^T (rank 16) ---
    // Reuse SMEM: ts/Bs need 128*17 = 2176 floats each; Xs holds 4224, Ws 4096.
    float* ts = &Xs[0][0][0];
    float* Bs = &Ws[0][0][0];
#pragma unroll
    for (int i = 0; i < 8; i++) {
        int idx = tid + i * 256;     // 0..2047
        int row = idx >> 4;
        int c   = idx & 15;
        ts[row * 17 + c] = g_t[(size_t)(m0 + row) * RANK + c];
        Bs[row * 17 + c] = loraB[(size_t)(n0 + row) * RANK + c];
    }
    __syncthreads();
#pragma unroll
    for (int r = 0; r < RANK; r++) {
        float ta[8], bb[8];
#pragma unroll
        for (int i = 0; i < 8; i++) ta[i] = ts[(ty * 8 + i) * 17 + r];
#pragma unroll
        for (int j = 0; j < 8; j++) bb[j] = Bs[(tx * 8 + j) * 17 + r];
#pragma unroll
        for (int i = 0; i < 8; i++)
#pragma unroll
            for (int j = 0; j < 8; j++)
                acc[i][j] = fmaf(ta[i], bb[j], acc[i][j]);
    }

    // --- write C ---
#pragma unroll
    for (int i = 0; i < 8; i++) {
        float* orow = out + (size_t)(m0 + ty * 8 + i) * OUT_F + n0 + tx * 8;
        float4 o0 = make_float4(acc[i][0], acc[i][1], acc[i][2], acc[i][3]);
        float4 o1 = make_float4(acc[i][4], acc[i][5], acc[i][6], acc[i][7]);
        *reinterpret_cast<float4*>(orow)     = o0;
        *reinterpret_cast<float4*>(orow + 4) = o1;
    }
}

// ---------------------------------------------------------------------------
// Harness entry. Inputs (metadata order):
//   0: x        [8192,4096] f32       1: qweight [512,4096] i32
//   2: qzeros   [32,512]    i32       3: scales  [32,4096]  f32
//   4: g_idx    [4096]      i32 (== k/128 by construction; unused)
//   5: lora_A   [16,4096]   f32       6: lora_B  [4096,16]  f32
// Output: [8192,4096] f32
// ---------------------------------------------------------------------------
extern "C" void kernel_launch(void* const* d_in, const int* in_sizes, int n_in,
                              void* d_out, int out_size)
{
    const float* x       = (const float*)d_in[0];
    const int*   qweight = (const int*)  d_in[1];
    const int*   qzeros  = (const int*)  d_in[2];
    const float* scales  = (const float*)d_in[3];
    const float* loraA   = (const float*)d_in[5];
    const float* loraB   = (const float*)d_in[6];
    float* out = (float*)d_out;

    lora_t_kernel<<<TOKENS / 64, 256>>>(x, loraA);

    dim3 grid(OUT_F / BN, TOKENS / BM);   // N fast-varying -> x stays L2-resident per wave
    fused_gemm_kernel<<<grid, 256>>>(x, qweight, qzeros, scales, loraB, out);
}

// round 6
// speedup vs baseline: 3.5915x; 3.5915x over previous
#include <cuda_runtime.h>
#include <cuda_fp16.h>
#include <cstdint>

#define TOKENS 8192
#define IN_F   4096
#define OUT_F  4096
#define RANK   16
#define LSCALE 2.0f

#define BM 128
#define BN 128
#define BK 64
#define NCHUNK (IN_F / BK)     // 64
#define NTH    512

// ---- dynamic smem layout (bytes) ----
#define STAGE_BYTES 49152      // A_h 16K + A_l 16K + B 16K
#define OFF_AH 0
#define OFF_AL 16384
#define OFF_B  32768
#define OFF_SC (3 * STAGE_BYTES)            // scales tile: 32 groups x 128 n x 4B
#define SMEM_TOTAL (OFF_SC + 32 * 128 * 4)  // 163840

// ---- scratch (device globals; allocation-free) ----
__device__ __half g_xh[(size_t)TOKENS * IN_F];   // 64 MB  x hi (fp16)
__device__ __half g_xl[(size_t)TOKENS * IN_F];   // 64 MB  x residual (fp16)
__device__ __half g_wq[(size_t)OUT_F * IN_F];    // 32 MB  q-(z+1) as fp16, [N][K]
__device__ float  g_t[TOKENS * RANK];            // LSCALE * (x @ A^T)

// ======================= asm helpers =======================
__device__ __forceinline__ uint32_t smem_u32(const void* p) {
    uint32_t a;
    asm("{ .reg .u64 t; cvta.to.shared.u64 t, %1; cvt.u32.u64 %0, t; }" : "=r"(a) : "l"(p));
    return a;
}
#define CP_ASYNC16(dst, src) \
    asm volatile("cp.async.cg.shared.global [%0], [%1], 16;" :: "r"(dst), "l"(src) : "memory")
#define CP_COMMIT() asm volatile("cp.async.commit_group;" ::: "memory")
#define CP_WAIT1()  asm volatile("cp.async.wait_group 1;" ::: "memory")

__device__ __forceinline__ void ldsm_x4(uint32_t* r, uint32_t addr) {
    asm volatile("ldmatrix.sync.aligned.m8n8.x4.shared.b16 {%0,%1,%2,%3}, [%4];"
                 : "=r"(r[0]), "=r"(r[1]), "=r"(r[2]), "=r"(r[3]) : "r"(addr));
}
__device__ __forceinline__ void mma_f16(float* d, const uint32_t* a,
                                        uint32_t b0, uint32_t b1, const float* c) {
    asm volatile("mma.sync.aligned.m16n8k16.row.col.f32.f16.f16.f32 "
                 "{%0,%1,%2,%3}, {%4,%5,%6,%7}, {%8,%9}, {%10,%11,%12,%13};"
                 : "=f"(d[0]), "=f"(d[1]), "=f"(d[2]), "=f"(d[3])
                 : "r"(a[0]), "r"(a[1]), "r"(a[2]), "r"(a[3]),
                   "r"(b0), "r"(b1),
                   "f"(c[0]), "f"(c[1]), "f"(c[2]), "f"(c[3]));
}

// ======================= prep kernels =======================
// x -> fp16 hi + fp16 residual
__global__ void __launch_bounds__(256) split_x_kernel(const float* __restrict__ x)
{
    const size_t idx = (size_t)blockIdx.x * 256 + threadIdx.x;   // float4 index
    float4 v = __ldg(reinterpret_cast<const float4*>(x) + idx);
    __half hx = __float2half_rn(v.x), hy = __float2half_rn(v.y);
    __half hz = __float2half_rn(v.z), hw = __float2half_rn(v.w);
    __half lx = __float2half_rn(v.x - __half2float(hx));
    __half ly = __float2half_rn(v.y - __half2float(hy));
    __half lz = __float2half_rn(v.z - __half2float(hz));
    __half lw = __float2half_rn(v.w - __half2float(hw));
    __half2* ph = reinterpret_cast<__half2*>(g_xh) + idx * 2;
    __half2* pl = reinterpret_cast<__half2*>(g_xl) + idx * 2;
    ph[0] = __halves2half2(hx, hy); ph[1] = __halves2half2(hz, hw);
    pl[0] = __halves2half2(lx, ly); pl[1] = __halves2half2(lz, lw);
}

// qweight [K/8][N] int32 -> g_wq [N][K] fp16 of (q - (z+1))
__global__ void __launch_bounds__(256) prep_wq_kernel(
    const int* __restrict__ qweight, const int* __restrict__ qzeros)
{
    const int idx = blockIdx.x * 256 + threadIdx.x;   // over 512*4096 words
    const int kp = idx >> 12;          // packed row (k/8)
    const int n  = idx & 4095;
    const int g  = kp >> 4;            // quant group (k/128)
    const int w  = __ldg(qweight + idx);
    const int zw = __ldg(qzeros + g * (OUT_F / 8) + (n >> 3));
    const int z  = ((zw >> (4 * (n & 7))) & 0xF) + 1;
    __half h[8];
#pragma unroll
    for (int i = 0; i < 8; i++)
        h[i] = __int2half_rn(((w >> (4 * i)) & 0xF) - z);
    *reinterpret_cast<uint4*>(g_wq + (size_t)n * IN_F + kp * 8) =
        *reinterpret_cast<uint4*>(h);
}

// t = LSCALE * x @ A^T   (coalesced SMEM-tiled)
#define LT_ROWS 32
__global__ void __launch_bounds__(256) lora_t_kernel(
    const float* __restrict__ x, const float* __restrict__ loraA)
{
    __shared__ float xs[LT_ROWS][132];   // pad 132: 16B-aligned rows, no bank conflicts
    __shared__ float as[RANK][132];
    const int tid  = threadIdx.x;
    const int m0   = blockIdx.x * LT_ROWS;
    const int r    = tid & 15;
    const int rowp = (tid >> 4) * 2;     // this thread handles rows rowp, rowp+1

    float acc0 = 0.f, acc1 = 0.f;
    for (int k0 = 0; k0 < IN_F; k0 += 128) {
        __syncthreads();
#pragma unroll
        for (int i = 0; i < 4; i++) {            // x tile: 1024 float4, coalesced
            const int f  = tid + i * 256;
            const int rr = f >> 5, cc = f & 31;
            *reinterpret_cast<float4*>(&xs[rr][cc * 4]) =
                __ldg(reinterpret_cast<const float4*>(x + (size_t)(m0 + rr) * IN_F + k0) + cc);
        }
#pragma unroll
        for (int i = 0; i < 2; i++) {            // A tile: 512 float4, coalesced
            const int f  = tid + i * 256;
            const int rr = f >> 5, cc = f & 31;
            *reinterpret_cast<float4*>(&as[rr][cc * 4]) =
                __ldg(reinterpret_cast<const float4*>(loraA + (size_t)rr * IN_F + k0) + cc);
        }
        __syncthreads();
#pragma unroll 8
        for (int kk = 0; kk < 128; kk++) {
            const float a = as[r][kk];
            acc0 = fmaf(xs[rowp][kk],     a, acc0);
            acc1 = fmaf(xs[rowp + 1][kk], a, acc1);
        }
    }
    g_t[(size_t)(m0 + rowp) * RANK + r]     = LSCALE * acc0;
    g_t[(size_t)(m0 + rowp + 1) * RANK + r] = LSCALE * acc1;
}

// ======================= main GEMM (mma.sync fp16 split-2, group-scaled) =====
__global__ void __launch_bounds__(NTH, 1) gemm_mma(
    const float* __restrict__ scales,   // [32][OUT_F]
    const float* __restrict__ loraB,    // [OUT_F][RANK]
    float*       __restrict__ out)
{
    extern __shared__ char smem[];
    const uint32_t sbase = smem_u32(smem);
    const int tid = threadIdx.x;
    const int l   = tid & 31;
    const int w   = tid >> 5;
    const int wm  = w >> 2;          // 0..3
    const int wn  = w & 3;           // 0..3
    const int n0  = blockIdx.x * BN;
    const int m0  = blockIdx.y * BM;

    // scales tile -> smem (32 groups x 128 n)
    float* sS = reinterpret_cast<float*>(smem + OFF_SC);
    for (int i = tid; i < 32 * 128; i += NTH)
        sS[i] = __ldg(scales + (size_t)(i >> 7) * OUT_F + n0 + (i & 127));

    // cp.async tile loader: 3 x 1024 16B-chunks per stage, 2 per thread per tile
    const __half* gAh = g_xh + (size_t)m0 * IN_F;
    const __half* gAl = g_xl + (size_t)m0 * IN_F;
    const __half* gB  = g_wq + (size_t)n0 * IN_F;
    auto load_chunk = [&](int c, int s) {
        const uint32_t sa = sbase + s * STAGE_BYTES;
        const int k0 = c * BK;
#pragma unroll
        for (int j = 0; j < 2; j++) {
            const int idx = tid + j * NTH;          // 0..1023
            const int row = idx >> 3;
            const int ch  = idx & 7;
            const uint32_t soff = row * 128 + ((ch ^ (row & 7)) << 4);
            CP_ASYNC16(sa + OFF_AH + soff, gAh + (size_t)row * IN_F + k0 + ch * 8);
            CP_ASYNC16(sa + OFF_AL + soff, gAl + (size_t)row * IN_F + k0 + ch * 8);
            CP_ASYNC16(sa + OFF_B  + soff, gB  + (size_t)row * IN_F + k0 + ch * 8);
        }
    };

    float acc[2][4][4];    // per-group accumulator (zeroed via C=0 first mma)
    float outr[2][4][4];   // scale-folded running output
#pragma unroll
    for (int mt = 0; mt < 2; mt++)
#pragma unroll
        for (int nt = 0; nt < 4; nt++)
#pragma unroll
            for (int i = 0; i < 4; i++) outr[mt][nt][i] = 0.f;
    const float zf[4] = {0.f, 0.f, 0.f, 0.f};

    // ldmatrix lane address components
    const int a_row = wm * 32 + (l & 15);                   // + mt*16
    const int a_chd = (l >> 4);                             // k-chunk +0/+1
    const int b_row = wn * 32 + (l & 7) + ((l & 16) >> 1);  // + pair*16
    const int b_chd = (l >> 3) & 1;

    load_chunk(0, 0); CP_COMMIT();
    load_chunk(1, 1); CP_COMMIT();

    for (int c = 0; c < NCHUNK; c++) {
        CP_WAIT1();
        __syncthreads();
        const int cn = c + 2;
        if (cn < NCHUNK) load_chunk(cn, cn % 3);
        CP_COMMIT();

        const uint32_t base = sbase + (c % 3) * STAGE_BYTES;
        const bool firstchunk = ((c & 1) == 0);
#pragma unroll
        for (int ks = 0; ks < 4; ks++) {
            const int kc0 = ks * 2;
            uint32_t ah[2][4], al[2][4];
#pragma unroll
            for (int mt = 0; mt < 2; mt++) {
                const int row = a_row + mt * 16;
                const int ch  = kc0 + a_chd;
                const uint32_t off = row * 128 + ((ch ^ (row & 7)) << 4);
                ldsm_x4(ah[mt], base + OFF_AH + off);
                ldsm_x4(al[mt], base + OFF_AL + off);
            }
            uint32_t bq[2][4];
#pragma unroll
            for (int p = 0; p < 2; p++) {
                const int row = b_row + p * 16;
                const int ch  = kc0 + b_chd;
                ldsm_x4(bq[p], base + OFF_B + row * 128 + ((ch ^ (row & 7)) << 4));
            }
            const bool first = firstchunk && (ks == 0);
#pragma unroll
            for (int mt = 0; mt < 2; mt++)
#pragma unroll
                for (int nt = 0; nt < 4; nt++) {
                    const uint32_t b0 = bq[nt >> 1][(nt & 1) * 2];
                    const uint32_t b1 = bq[nt >> 1][(nt & 1) * 2 + 1];
                    float* A = acc[mt][nt];
                    mma_f16(A, ah[mt], b0, b1, first ? zf : A);
                    mma_f16(A, al[mt], b0, b1, A);
                }
        }

        if (c & 1) {   // end of 128-deep quant group: out += s * acc
            const int g = c >> 1;
#pragma unroll
            for (int nt = 0; nt < 4; nt++) {
                const float2 sv = *reinterpret_cast<const float2*>(
                    sS + g * 128 + wn * 32 + nt * 8 + (l & 3) * 2);
#pragma unroll
                for (int mt = 0; mt < 2; mt++) {
#pragma unroll
                    for (int i = 0; i < 4; i++)
                        outr[mt][nt][i] = fmaf((i & 1) ? sv.y : sv.x,
                                               acc[mt][nt][i], outr[mt][nt][i]);
                }
            }
        }
    }

    // ---------------- epilogue: LoRA + writeback ----------------
    __syncthreads();
    float* ts = reinterpret_cast<float*>(smem);          // [128][16]
    float* Bs = reinterpret_cast<float*>(smem + 8192);   // [128][16]
    for (int i = tid; i < BM * RANK; i += NTH) {
        ts[i] = g_t[(size_t)(m0 + (i >> 4)) * RANK + (i & 15)];
        Bs[i] = __ldg(loraB + (size_t)(n0 + (i >> 4)) * RANK + (i & 15));
    }
    __syncthreads();

#pragma unroll
    for (int mt = 0; mt < 2; mt++) {
#pragma unroll
        for (int rh = 0; rh < 2; rh++) {
            const int ml = wm * 32 + mt * 16 + (l >> 2) + rh * 8;
            const float4* tp = reinterpret_cast<const float4*>(ts + ml * RANK);
            const float4 t0 = tp[0], t1 = tp[1], t2 = tp[2], t3 = tp[3];
            float* orow = out + (size_t)(m0 + ml) * OUT_F + n0;
#pragma unroll
            for (int nt = 0; nt < 4; nt++) {
                const int nl = wn * 32 + nt * 8 + (l & 3) * 2;
                float v[2];
#pragma unroll
                for (int cc = 0; cc < 2; cc++) {
                    const float4* bp = reinterpret_cast<const float4*>(Bs + (nl + cc) * RANK);
                    const float4 b0 = bp[0], b1 = bp[1], b2 = bp[2], b3 = bp[3];
                    float d = t0.x * b0.x;
                    d = fmaf(t0.y, b0.y, d); d = fmaf(t0.z, b0.z, d); d = fmaf(t0.w, b0.w, d);
                    d = fmaf(t1.x, b1.x, d); d = fmaf(t1.y, b1.y, d); d = fmaf(t1.z, b1.z, d);
                    d = fmaf(t1.w, b1.w, d); d = fmaf(t2.x, b2.x, d); d = fmaf(t2.y, b2.y, d);
                    d = fmaf(t2.z, b2.z, d); d = fmaf(t2.w, b2.w, d); d = fmaf(t3.x, b3.x, d);
                    d = fmaf(t3.y, b3.y, d); d = fmaf(t3.z, b3.z, d); d = fmaf(t3.w, b3.w, d);
                    v[cc] = outr[mt][nt][rh * 2 + cc] + d;
                }
                *reinterpret_cast<float2*>(orow + nl) = make_float2(v[0], v[1]);
            }
        }
    }
}

// ======================= launch =======================
extern "C" void kernel_launch(void* const* d_in, const int* in_sizes, int n_in,
                              void* d_out, int out_size)
{
    const float* x       = (const float*)d_in[0];
    const int*   qweight = (const int*)  d_in[1];
    const int*   qzeros  = (const int*)  d_in[2];
    const float* scales  = (const float*)d_in[3];
    const float* loraA   = (const float*)d_in[5];
    const float* loraB   = (const float*)d_in[6];
    float* out = (float*)d_out;

    cudaFuncSetAttribute(gemm_mma,
                         cudaFuncAttributeMaxDynamicSharedMemorySize, SMEM_TOTAL);

    split_x_kernel<<<(TOKENS * (IN_F / 4)) / 256, 256>>>(x);
    prep_wq_kernel<<<((IN_F / 8) * OUT_F) / 256, 256>>>(qweight, qzeros);
    lora_t_kernel<<<TOKENS / LT_ROWS, 256>>>(x, loraA);

    dim3 grid(OUT_F / BN, TOKENS / BM);   // N fast -> x slab stays L2-resident per wave
    gemm_mma<<<grid, NTH, SMEM_TOTAL>>>(scales, loraB, out);
}